// round 4
// baseline (speedup 1.0000x reference)
#include <cuda_runtime.h>
#include <math.h>

// Problem constants
#define B_  2
#define C_  64
#define H_  128
#define W_  128
#define HW_ (H_*W_)          // 16384
#define HID 16
#define OFC 18
#define NPT 9
#define KTOT (C_*NPT)        // 576
#define PIXT (B_*HW_)        // 32768

// ---- device scratch (no runtime allocation allowed) ----
__device__ float g_f  [B_*HID*HW_];   // offset-branch feature  [B,16,H,W]
__device__ float g_off[B_*OFC*HW_];   // offsets                [B,18,H,W]
__device__ float g_wt [KTOT*C_];      // transposed w_out       [576][64]

// ============================================================
// K0: transpose w_out (oc,ic,3,3) -> g_wt[k][oc], k = ic*9 + i*3 + j
// ============================================================
__global__ void k0_transpose(const float* __restrict__ w) {
    int e = blockIdx.x * 256 + threadIdx.x;     // 36864 total
    if (e < KTOT * C_) {
        int oc = e / KTOT, k = e % KTOT;
        g_wt[k * C_ + oc] = w[e];
    }
}

// ============================================================
// K1: f = relu(bn(conv1x1_{64->16}(x)))
// ============================================================
__global__ void k1_conv1(const float* __restrict__ x,
                         const float* __restrict__ w1,
                         const float* __restrict__ g1,
                         const float* __restrict__ b1,
                         const float* __restrict__ m1,
                         const float* __restrict__ v1) {
    __shared__ float ws[C_][HID];       // [c][o]
    __shared__ float inv_s[HID], beta_s[HID];
    int tid = threadIdx.x;
    for (int e = tid; e < HID * C_; e += 256) {
        int o = e / C_, c = e % C_;
        ws[c][o] = w1[e];
    }
    if (tid < HID) {
        float inv = g1[tid] * rsqrtf(v1[tid] + 1e-5f);
        inv_s[tid] = inv;
        beta_s[tid] = b1[tid] - m1[tid] * inv;
    }
    __syncthreads();

    int p = blockIdx.x * 256 + tid;           // pixel id
    int b = p >> 14, hw = p & (HW_ - 1);
    const float* xb = x + (size_t)b * C_ * HW_ + hw;

    float acc[HID];
#pragma unroll
    for (int o = 0; o < HID; o++) acc[o] = 0.f;
    for (int c = 0; c < C_; c++) {
        float xv = xb[c * HW_];
#pragma unroll
        for (int o = 0; o < HID; o++) acc[o] += ws[c][o] * xv;
    }
    float* fb = g_f + (size_t)b * HID * HW_ + hw;
#pragma unroll
    for (int o = 0; o < HID; o++)
        fb[o * HW_] = fmaxf(acc[o] * inv_s[o] + beta_s[o], 0.f);
}

// ============================================================
// K2: off = relu(bn3(conv1x1_{18->18}( relu(bn2(conv3x3_{16->18}(f))) )))
// ============================================================
__global__ void k2_offsets(const float* __restrict__ wdw,
                           const float* __restrict__ g2, const float* __restrict__ b2,
                           const float* __restrict__ m2, const float* __restrict__ v2,
                           const float* __restrict__ wc2,
                           const float* __restrict__ g3, const float* __restrict__ b3,
                           const float* __restrict__ m3, const float* __restrict__ v3) {
    __shared__ float wdw_s[OFC * HID * 9];   // same flat layout as global: o*144+ci*9+k
    __shared__ float wc2_s[OFC * OFC];
    __shared__ float inv2_s[OFC], beta2_s[OFC], inv3_s[OFC], beta3_s[OFC];
    int tid = threadIdx.x;
    for (int e = tid; e < OFC * HID * 9; e += 256) wdw_s[e] = wdw[e];
    for (int e = tid; e < OFC * OFC; e += 256)     wc2_s[e] = wc2[e];
    if (tid < OFC) {
        float i2 = g2[tid] * rsqrtf(v2[tid] + 1e-5f);
        inv2_s[tid] = i2; beta2_s[tid] = b2[tid] - m2[tid] * i2;
        float i3 = g3[tid] * rsqrtf(v3[tid] + 1e-5f);
        inv3_s[tid] = i3; beta3_s[tid] = b3[tid] - m3[tid] * i3;
    }
    __syncthreads();

    int p = blockIdx.x * 256 + tid;
    int b = p >> 14, hw = p & (HW_ - 1);
    int h = hw >> 7, w = hw & (W_ - 1);

    float acc[OFC];
#pragma unroll
    for (int o = 0; o < OFC; o++) acc[o] = 0.f;

    const float* fb = g_f + (size_t)b * HID * HW_;
    for (int ci = 0; ci < HID; ci++) {
        float fv[9];
#pragma unroll
        for (int dh = 0; dh < 3; dh++)
#pragma unroll
            for (int dw = 0; dw < 3; dw++) {
                int hh = h + dh - 1, ww = w + dw - 1;
                fv[dh * 3 + dw] = (hh >= 0 && hh < H_ && ww >= 0 && ww < W_)
                                  ? fb[ci * HW_ + hh * W_ + ww] : 0.f;
            }
        const float* wp = wdw_s + ci * 9;
#pragma unroll
        for (int o = 0; o < OFC; o++) {
            const float* wo = wp + o * (HID * 9);
            float a = acc[o];
#pragma unroll
            for (int k = 0; k < 9; k++) a += wo[k] * fv[k];
            acc[o] = a;
        }
    }
    float t[OFC];
#pragma unroll
    for (int o = 0; o < OFC; o++)
        t[o] = fmaxf(acc[o] * inv2_s[o] + beta2_s[o], 0.f);

    float* op = g_off + (size_t)b * OFC * HW_ + hw;
#pragma unroll
    for (int o2 = 0; o2 < OFC; o2++) {
        float a = 0.f;
#pragma unroll
        for (int o = 0; o < OFC; o++) a += wc2_s[o2 * OFC + o] * t[o];
        op[o2 * HW_] = fmaxf(a * inv3_s[o2] + beta3_s[o2], 0.f);
    }
}

// ============================================================
// K3: fused bilinear sampler + SGEMM + residual
//   block = 8x8 pixel tile (64 px) x all 64 output channels, 256 threads
//   smem: w_s[576][64] (full weights) + a_s[72][64] (x_off slab)
//         + per-point bilinear meta (idx4 + wgt4 for 64 px x 9 pts)
// ============================================================
#define K3_SMEM ((KTOT*C_ + 72*64) * 4 + 64*NPT*32)

__global__ __launch_bounds__(256, 1)
void k3_main(const float* __restrict__ x, float* __restrict__ out) {
    extern __shared__ float smem[];
    float* w_s = smem;                               // [576][64]
    float* a_s = smem + KTOT * C_;                   // [72][64]
    int4*  idx_s = (int4*)(smem + KTOT * C_ + 72 * 64);  // [64*9]
    float4* wgt_s = (float4*)(idx_s + 64 * NPT);         // [64*9]

    int tid = threadIdx.x;
    int blk = blockIdx.x;            // 512 blocks
    int b = blk >> 8;
    int tile = blk & 255;
    int h0 = (tile >> 4) << 3;
    int w0 = (tile & 15) << 3;

    // load transposed weights (coalesced, conflict-free)
    for (int e = tid; e < KTOT * C_; e += 256) w_s[e] = g_wt[e];

    // per-point bilinear metadata for this tile's 64 pixels x 9 points
    const float* offp = g_off + (size_t)b * OFC * HW_;
    for (int e = tid; e < 64 * NPT; e += 256) {
        int m = e / NPT, n = e - m * NPT;
        int h = h0 + (m >> 3), w = w0 + (m & 7);
        int hw = h * W_ + w;
        float offx = offp[n * HW_ + hw];
        float offy = offp[(NPT + n) * HW_ + hw];
        float px = (float)(h + 1) + (float)(n / 3 - 1) + offx;
        float py = (float)(w + 1) + (float)(n % 3 - 1) + offy;
        float flx = floorf(px), fly = floorf(py);
        float qltx = fminf(fmaxf(flx, 0.f), 129.f);
        float qlty = fminf(fmaxf(fly, 0.f), 129.f);
        float qrbx = fminf(fmaxf(flx + 1.f, 0.f), 129.f);
        float qrby = fminf(fmaxf(fly + 1.f, 0.f), 129.f);
        px = fminf(fmaxf(px, 0.f), 129.f);
        py = fminf(fmaxf(py, 0.f), 129.f);
        float gx_lt = 1.f + qltx - px, gx_rb = 1.f - qrbx + px;
        float gy_lt = 1.f + qlty - py, gy_rb = 1.f - qrby + py;
        float4 g;
        g.x = gx_lt * gy_lt;   // lt
        g.y = gx_rb * gy_rb;   // rb
        g.z = gx_lt * gy_rb;   // lb
        g.w = gx_rb * gy_lt;   // rt
        int ltx = (int)qltx, lty = (int)qlty, rbx = (int)qrbx, rby = (int)qrby;
        int4 id;
        id.x = (ltx >= 1 && ltx <= H_ && lty >= 1 && lty <= W_) ? ((ltx - 1) * W_ + (lty - 1)) : -1;
        id.y = (rbx >= 1 && rbx <= H_ && rby >= 1 && rby <= W_) ? ((rbx - 1) * W_ + (rby - 1)) : -1;
        id.z = (ltx >= 1 && ltx <= H_ && rby >= 1 && rby <= W_) ? ((ltx - 1) * W_ + (rby - 1)) : -1;
        id.w = (rbx >= 1 && rbx <= H_ && lty >= 1 && lty <= W_) ? ((rbx - 1) * W_ + (lty - 1)) : -1;
        idx_s[e] = id;
        wgt_s[e] = g;
    }

    float acc[4][4];
#pragma unroll
    for (int i = 0; i < 4; i++)
#pragma unroll
        for (int j = 0; j < 4; j++) acc[i][j] = 0.f;

    int tx = tid & 15, ty = tid >> 4;
    const float* xb = x + (size_t)b * C_ * HW_;

    for (int c0 = 0; c0 < C_; c0 += 8) {
        __syncthreads();     // a_s free (prev GEMM done) & meta ready (iter 0)

        // gather x_off slab: a_s[k][m], k = (ci-c0)*9 + n, m = pixel
        for (int e = tid; e < 72 * 64; e += 256) {
            int k = e >> 6, m = e & 63;
            int ci = c0 + (k / NPT), n = k - (k / NPT) * NPT;
            const float* xc = xb + ci * HW_;
            int4 id = idx_s[m * NPT + n];
            float4 g = wgt_s[m * NPT + n];
            float v = 0.f;
            if (id.x >= 0) v += g.x * xc[id.x];
            if (id.y >= 0) v += g.y * xc[id.y];
            if (id.z >= 0) v += g.z * xc[id.z];
            if (id.w >= 0) v += g.w * xc[id.w];
            a_s[e] = v;
        }
        __syncthreads();

        const float* wrow = w_s + c0 * NPT * C_;
#pragma unroll 8
        for (int k = 0; k < 72; k++) {
            float4 av = *reinterpret_cast<const float4*>(a_s + (k << 6) + (ty << 2));
            float4 bv = *reinterpret_cast<const float4*>(wrow + (k << 6) + (tx << 2));
            acc[0][0] += av.x * bv.x; acc[0][1] += av.x * bv.y; acc[0][2] += av.x * bv.z; acc[0][3] += av.x * bv.w;
            acc[1][0] += av.y * bv.x; acc[1][1] += av.y * bv.y; acc[1][2] += av.y * bv.z; acc[1][3] += av.y * bv.w;
            acc[2][0] += av.z * bv.x; acc[2][1] += av.z * bv.y; acc[2][2] += av.z * bv.z; acc[2][3] += av.z * bv.w;
            acc[3][0] += av.w * bv.x; acc[3][1] += av.w * bv.y; acc[3][2] += av.w * bv.z; acc[3][3] += av.w * bv.w;
        }
    }

    // epilogue: out = identity + conv
#pragma unroll
    for (int pi = 0; pi < 4; pi++) {
        int m = (ty << 2) + pi;
        int h = h0 + (m >> 3), w = w0 + (m & 7);
        int base = b * C_ * HW_ + h * W_ + w;
#pragma unroll
        for (int ni = 0; ni < 4; ni++) {
            int oc = (tx << 2) + ni;
            int gi = base + oc * HW_;
            out[gi] = x[gi] + acc[pi][ni];
        }
    }
}

// ============================================================
extern "C" void kernel_launch(void* const* d_in, const int* in_sizes, int n_in,
                              void* d_out, int out_size) {
    const float* x       = (const float*)d_in[0];
    const float* w_conv1 = (const float*)d_in[1];
    const float* g1 = (const float*)d_in[2];
    const float* b1 = (const float*)d_in[3];
    const float* m1 = (const float*)d_in[4];
    const float* v1 = (const float*)d_in[5];
    const float* w_dw = (const float*)d_in[6];
    const float* g2 = (const float*)d_in[7];
    const float* b2 = (const float*)d_in[8];
    const float* m2 = (const float*)d_in[9];
    const float* v2 = (const float*)d_in[10];
    const float* w_conv2 = (const float*)d_in[11];
    const float* g3 = (const float*)d_in[12];
    const float* b3 = (const float*)d_in[13];
    const float* m3 = (const float*)d_in[14];
    const float* v3 = (const float*)d_in[15];
    const float* w_out = (const float*)d_in[16];
    float* out = (float*)d_out;

    cudaFuncSetAttribute(k3_main, cudaFuncAttributeMaxDynamicSharedMemorySize, K3_SMEM);

    k0_transpose<<<144, 256>>>(w_out);
    k1_conv1<<<PIXT / 256, 256>>>(x, w_conv1, g1, b1, m1, v1);
    k2_offsets<<<PIXT / 256, 256>>>(w_dw, g2, b2, m2, v2, w_conv2, g3, b3, m3, v3);
    k3_main<<<B_ * (H_ / 8) * (W_ / 8), 256, K3_SMEM>>>(x, out);
}

// round 5
// speedup vs baseline: 1.2938x; 1.2938x over previous
#include <cuda_runtime.h>
#include <math.h>

// Problem constants
#define B_  2
#define C_  64
#define H_  128
#define W_  128
#define HW_ (H_*W_)          // 16384
#define HID 16
#define OFC 18
#define NPT 9
#define KTOT (C_*NPT)        // 576
#define PIXT (B_*HW_)        // 32768
#define HP_  130
#define WP_  130
#define HWP_ (HP_*WP_)       // 16900

// ---- device scratch (no runtime allocation allowed) ----
__device__ float g_f  [B_*HID*HW_];     // offset-branch feature [B,16,H,W]
__device__ float g_off[B_*OFC*HW_];     // offsets               [B,18,H,W]
__device__ float g_wt [KTOT*C_ + 64];   // transposed w_out [576][64] (+pad)
__device__ float g_xp [B_*C_*HWP_];     // zero-padded input [B,C,130,130]

// packed fp32x2 FMA (full-rate on sm_103a; scalar FFMA is half-rate)
#define FMA2(d,a,b) asm("fma.rn.f32x2 %0, %1, %2, %0;" : "+l"(d) : "l"(a), "l"(b))

// ============================================================
// K0: transpose w_out (oc,ic,3,3) -> g_wt[k][oc], k = ic*9 + i*3 + j
// ============================================================
__global__ void k0_transpose(const float* __restrict__ w) {
    int e = blockIdx.x * 256 + threadIdx.x;
    if (e < KTOT * C_) {
        int oc = e / KTOT, k = e % KTOT;
        g_wt[k * C_ + oc] = w[e];
    }
}

// ============================================================
// K_pad: g_xp = zero-pad(x) by 1 on each side
// ============================================================
__global__ void k_pad(const float* __restrict__ x) {
    int e = blockIdx.x * 256 + threadIdx.x;
    if (e >= B_ * C_ * HWP_) return;
    int bc = e / HWP_, r = e - bc * HWP_;
    int h = r / WP_, w = r - h * WP_;
    float v = 0.f;
    if (h >= 1 && h <= H_ && w >= 1 && w <= W_)
        v = x[bc * HW_ + (h - 1) * W_ + (w - 1)];
    g_xp[e] = v;
}

// ============================================================
// K1: f = relu(bn(conv1x1_{64->16}(x)))
// ============================================================
__global__ void k1_conv1(const float* __restrict__ x,
                         const float* __restrict__ w1,
                         const float* __restrict__ g1,
                         const float* __restrict__ b1,
                         const float* __restrict__ m1,
                         const float* __restrict__ v1) {
    __shared__ float ws[C_][HID];
    __shared__ float inv_s[HID], beta_s[HID];
    int tid = threadIdx.x;
    for (int e = tid; e < HID * C_; e += 256) {
        int o = e / C_, c = e % C_;
        ws[c][o] = w1[e];
    }
    if (tid < HID) {
        float inv = g1[tid] * rsqrtf(v1[tid] + 1e-5f);
        inv_s[tid] = inv;
        beta_s[tid] = b1[tid] - m1[tid] * inv;
    }
    __syncthreads();

    int p = blockIdx.x * 256 + tid;
    int b = p >> 14, hw = p & (HW_ - 1);
    const float* xb = x + (size_t)b * C_ * HW_ + hw;

    float acc[HID];
#pragma unroll
    for (int o = 0; o < HID; o++) acc[o] = 0.f;
    for (int c = 0; c < C_; c++) {
        float xv = xb[c * HW_];
#pragma unroll
        for (int o = 0; o < HID; o++) acc[o] += ws[c][o] * xv;
    }
    float* fb = g_f + (size_t)b * HID * HW_ + hw;
#pragma unroll
    for (int o = 0; o < HID; o++)
        fb[o * HW_] = fmaxf(acc[o] * inv_s[o] + beta_s[o], 0.f);
}

// ============================================================
// K2: off = relu(bn3(conv1x1_{18->18}( relu(bn2(conv3x3_{16->18}(f))) )))
// ============================================================
__global__ void k2_offsets(const float* __restrict__ wdw,
                           const float* __restrict__ g2, const float* __restrict__ b2,
                           const float* __restrict__ m2, const float* __restrict__ v2,
                           const float* __restrict__ wc2,
                           const float* __restrict__ g3, const float* __restrict__ b3,
                           const float* __restrict__ m3, const float* __restrict__ v3) {
    __shared__ float wdw_s[OFC * HID * 9];
    __shared__ float wc2_s[OFC * OFC];
    __shared__ float inv2_s[OFC], beta2_s[OFC], inv3_s[OFC], beta3_s[OFC];
    int tid = threadIdx.x;
    for (int e = tid; e < OFC * HID * 9; e += 256) wdw_s[e] = wdw[e];
    for (int e = tid; e < OFC * OFC; e += 256)     wc2_s[e] = wc2[e];
    if (tid < OFC) {
        float i2 = g2[tid] * rsqrtf(v2[tid] + 1e-5f);
        inv2_s[tid] = i2; beta2_s[tid] = b2[tid] - m2[tid] * i2;
        float i3 = g3[tid] * rsqrtf(v3[tid] + 1e-5f);
        inv3_s[tid] = i3; beta3_s[tid] = b3[tid] - m3[tid] * i3;
    }
    __syncthreads();

    int p = blockIdx.x * 256 + tid;
    int b = p >> 14, hw = p & (HW_ - 1);
    int h = hw >> 7, w = hw & (W_ - 1);

    float acc[OFC];
#pragma unroll
    for (int o = 0; o < OFC; o++) acc[o] = 0.f;

    const float* fb = g_f + (size_t)b * HID * HW_;
    for (int ci = 0; ci < HID; ci++) {
        float fv[9];
#pragma unroll
        for (int dh = 0; dh < 3; dh++)
#pragma unroll
            for (int dw = 0; dw < 3; dw++) {
                int hh = h + dh - 1, ww = w + dw - 1;
                fv[dh * 3 + dw] = (hh >= 0 && hh < H_ && ww >= 0 && ww < W_)
                                  ? fb[ci * HW_ + hh * W_ + ww] : 0.f;
            }
        const float* wp = wdw_s + ci * 9;
#pragma unroll
        for (int o = 0; o < OFC; o++) {
            const float* wo = wp + o * (HID * 9);
            float a = acc[o];
#pragma unroll
            for (int k = 0; k < 9; k++) a += wo[k] * fv[k];
            acc[o] = a;
        }
    }
    float t[OFC];
#pragma unroll
    for (int o = 0; o < OFC; o++)
        t[o] = fmaxf(acc[o] * inv2_s[o] + beta2_s[o], 0.f);

    float* op = g_off + (size_t)b * OFC * HW_ + hw;
#pragma unroll
    for (int o2 = 0; o2 < OFC; o2++) {
        float a = 0.f;
#pragma unroll
        for (int o = 0; o < OFC; o++) a += wc2_s[o2 * OFC + o] * t[o];
        op[o2 * HW_] = fmaxf(a * inv3_s[o2] + beta3_s[o2], 0.f);
    }
}

// ============================================================
// K3: fused bilinear sampler + SGEMM (f32x2) + residual
//   block = 8x8 pixel tile (64 px) x all 64 oc, 256 threads, 2 CTAs/SM
//   smem: meta (idx4+wgt4, 18KB) + double-buffered DUPLICATED A slab
//         a2[2][72][128] (a2[k][2m]=a2[k][2m+1]=value) = 72KB  -> 92KB total
//   B operand (g_wt rows) streamed from L2 (shared by all blocks).
// ============================================================
#define A2N (72*128)
#define K3_SMEM (576*32 + 2*A2N*4)   // 18432 + 73728 = 92160

__global__ __launch_bounds__(256, 2)
void k3_main(const float* __restrict__ x, float* __restrict__ out) {
    extern __shared__ char smem[];
    int4*   idx_s = (int4*)smem;                   // [9][64]
    float4* wgt_s = (float4*)(smem + 9216);        // [9][64]
    float*  a2    = (float*)(smem + 18432);        // [2][72][128]

    int tid = threadIdx.x;
    int blk = blockIdx.x;
    int b = blk >> 8;
    int tile = blk & 255;
    int h0 = (tile >> 4) << 3;
    int w0 = (tile & 15) << 3;

    // ---- bilinear metadata for 64 px x 9 pts (indices into padded image) ----
    const float* offp = g_off + (size_t)b * OFC * HW_;
    for (int e = tid; e < 64 * NPT; e += 256) {
        int m = e / NPT, n = e - m * NPT;
        int h = h0 + (m >> 3), w = w0 + (m & 7);
        int hw = h * W_ + w;
        float offx = offp[n * HW_ + hw];
        float offy = offp[(NPT + n) * HW_ + hw];
        float px = (float)(h + 1) + (float)(n / 3 - 1) + offx;
        float py = (float)(w + 1) + (float)(n % 3 - 1) + offy;
        float flx = floorf(px), fly = floorf(py);
        float qltx = fminf(fmaxf(flx, 0.f), 129.f);
        float qlty = fminf(fmaxf(fly, 0.f), 129.f);
        float qrbx = fminf(fmaxf(flx + 1.f, 0.f), 129.f);
        float qrby = fminf(fmaxf(fly + 1.f, 0.f), 129.f);
        px = fminf(fmaxf(px, 0.f), 129.f);
        py = fminf(fmaxf(py, 0.f), 129.f);
        float gxl = 1.f + qltx - px, gxr = 1.f - qrbx + px;
        float gyl = 1.f + qlty - py, gyr = 1.f - qrby + py;
        float4 g;
        g.x = gxl * gyl; g.y = gxr * gyr; g.z = gxl * gyr; g.w = gxr * gyl;
        int ltx = (int)qltx, lty = (int)qlty, rbx = (int)qrbx, rby = (int)qrby;
        int4 id;
        id.x = ltx * WP_ + lty;
        id.y = rbx * WP_ + rby;
        id.z = ltx * WP_ + rby;
        id.w = rbx * WP_ + lty;
        idx_s[n * 64 + m] = id;     // [n][m] layout: conflict-free gather reads
        wgt_s[n * 64 + m] = g;
    }
    __syncthreads();

    const float* xpb = g_xp + (size_t)b * C_ * HWP_;

    // ---- gather chunk 0 into buffer 0 (values stored DUPLICATED) ----
    {
        float* ab = a2;
        for (int e = tid; e < 72 * 64; e += 256) {
            int k = e >> 6, m = e & 63;
            int ci = k / NPT, n = k - ci * NPT;
            const float* xc = xpb + ci * HWP_;
            int4 id = idx_s[n * 64 + m];
            float4 g = wgt_s[n * 64 + m];
            float v = g.x * xc[id.x] + g.y * xc[id.y]
                    + g.z * xc[id.z] + g.w * xc[id.w];
            float2 vv = make_float2(v, v);
            *reinterpret_cast<float2*>(ab + (k << 7) + (m << 1)) = vv;
        }
    }

    int tx = tid & 15, ty = tid >> 4;
    unsigned long long acc[4][2];
#pragma unroll
    for (int i = 0; i < 4; i++) { acc[i][0] = 0ull; acc[i][1] = 0ull; }

    const int tyo = ty << 3;
    const int txo = tx << 2;

    // ---- pipelined chunk loop: gather(c+1) overlaps GEMM(c) ----
    for (int c = 0; c < 8; c++) {
        __syncthreads();

        if (c < 7) {
            float* ab = a2 + ((c + 1) & 1) * A2N;
            int cbase = (c + 1) * 8;
            for (int e = tid; e < 72 * 64; e += 256) {
                int k = e >> 6, m = e & 63;
                int kc = k / NPT, n = k - kc * NPT;
                const float* xc = xpb + (cbase + kc) * HWP_;
                int4 id = idx_s[n * 64 + m];
                float4 g = wgt_s[n * 64 + m];
                float v = g.x * xc[id.x] + g.y * xc[id.y]
                        + g.z * xc[id.z] + g.w * xc[id.w];
                float2 vv = make_float2(v, v);
                *reinterpret_cast<float2*>(ab + (k << 7) + (m << 1)) = vv;
            }
        }

        const float* ab = a2 + (c & 1) * A2N;
        const float* wp = g_wt + c * 8 * NPT * C_ + txo;   // B rows in L2
#pragma unroll 8
        for (int k = 0; k < 72; k++) {
            ulonglong2 bb = *reinterpret_cast<const ulonglong2*>(wp + (k << 6));
            ulonglong2 aA = *reinterpret_cast<const ulonglong2*>(ab + (k << 7) + tyo);
            ulonglong2 aB = *reinterpret_cast<const ulonglong2*>(ab + (k << 7) + tyo + 4);
            FMA2(acc[0][0], aA.x, bb.x); FMA2(acc[0][1], aA.x, bb.y);
            FMA2(acc[1][0], aA.y, bb.x); FMA2(acc[1][1], aA.y, bb.y);
            FMA2(acc[2][0], aB.x, bb.x); FMA2(acc[2][1], aB.x, bb.y);
            FMA2(acc[3][0], aB.y, bb.x); FMA2(acc[3][1], aB.y, bb.y);
        }
    }

    // ---- epilogue: stage through smem for coalesced residual stores ----
    // buf0 is dead after GEMM chunk 6 (chunk 7 reads buf1); reuse it.
    float* sa = a2;  // [oc][m] : 64*64 floats
#pragma unroll
    for (int pi = 0; pi < 4; pi++) {
        int m = (ty << 2) + pi;
#pragma unroll
        for (int j = 0; j < 2; j++) {
            unsigned long long v = acc[pi][j];
            float lo = __uint_as_float((unsigned)(v & 0xffffffffull));
            float hi = __uint_as_float((unsigned)(v >> 32));
            sa[(txo + 2 * j) * 64 + m]     = lo;
            sa[(txo + 2 * j + 1) * 64 + m] = hi;
        }
    }
    __syncthreads();

    for (int e = tid; e < 64 * 64; e += 256) {
        int oc = e >> 6, m = e & 63;
        int h = h0 + (m >> 3), w = w0 + (m & 7);
        int gi = ((b * C_ + oc) * H_ + h) * W_ + w;
        out[gi] = x[gi] + sa[e];
    }
}

// ============================================================
extern "C" void kernel_launch(void* const* d_in, const int* in_sizes, int n_in,
                              void* d_out, int out_size) {
    const float* x       = (const float*)d_in[0];
    const float* w_conv1 = (const float*)d_in[1];
    const float* g1 = (const float*)d_in[2];
    const float* b1 = (const float*)d_in[3];
    const float* m1 = (const float*)d_in[4];
    const float* v1 = (const float*)d_in[5];
    const float* w_dw = (const float*)d_in[6];
    const float* g2 = (const float*)d_in[7];
    const float* b2 = (const float*)d_in[8];
    const float* m2 = (const float*)d_in[9];
    const float* v2 = (const float*)d_in[10];
    const float* w_conv2 = (const float*)d_in[11];
    const float* g3 = (const float*)d_in[12];
    const float* b3 = (const float*)d_in[13];
    const float* m3 = (const float*)d_in[14];
    const float* v3 = (const float*)d_in[15];
    const float* w_out = (const float*)d_in[16];
    float* out = (float*)d_out;

    cudaFuncSetAttribute(k3_main, cudaFuncAttributeMaxDynamicSharedMemorySize, K3_SMEM);

    k0_transpose<<<144, 256>>>(w_out);
    k_pad<<<(B_*C_*HWP_ + 255) / 256, 256>>>(x);
    k1_conv1<<<PIXT / 256, 256>>>(x, w_conv1, g1, b1, m1, v1);
    k2_offsets<<<PIXT / 256, 256>>>(w_dw, g2, b2, m2, v2, w_conv2, g3, b3, m3, v3);
    k3_main<<<B_ * (H_ / 8) * (W_ / 8), 256, K3_SMEM>>>(x, out);
}

// round 6
// speedup vs baseline: 1.4466x; 1.1181x over previous
#include <cuda_runtime.h>
#include <math.h>

// Problem constants
#define B_  2
#define C_  64
#define H_  128
#define W_  128
#define HW_ (H_*W_)          // 16384
#define HID 16
#define OFC 18
#define NPT 9
#define KTOT (C_*NPT)        // 576
#define PIXT (B_*HW_)        // 32768
#define HP_  130
#define WP_  130
#define HWP_ (HP_*WP_)       // 16900

// ---- device scratch (no runtime allocation allowed) ----
__device__ float g_f  [B_*HID*HW_];     // offset-branch feature [B,16,H,W]
__device__ float g_off[B_*OFC*HW_];     // offsets               [B,18,H,W]
__device__ float g_wt [KTOT*C_ + 64];   // permuted w_out: row R=(c*72 + n*8 + cil), col oc
__device__ float g_xp [B_*C_*HWP_];     // zero-padded input [B,C,130,130]

// packed fp32x2 FMA (full-rate on sm_103a; scalar FFMA is half-rate)
#define FMA2(d,a,b) asm("fma.rn.f32x2 %0, %1, %2, %0;" : "+l"(d) : "l"(a), "l"(b))

// ============================================================
// K_pad0: zero-pad x into g_xp  AND  permute-transpose w_out into g_wt
//   g_wt row R = c*72 + n*8 + cil  (c = ci>>3, cil = ci&7, k_orig = ci*9+n)
// ============================================================
#define PAD_ELEMS (B_*C_*HWP_)
__global__ void k_pad0(const float* __restrict__ x, const float* __restrict__ w) {
    int e = blockIdx.x * 256 + threadIdx.x;
    if (e < PAD_ELEMS) {
        int bc = e / HWP_, r = e - bc * HWP_;
        int h = r / WP_, w2 = r - h * WP_;
        float v = 0.f;
        if (h >= 1 && h <= H_ && w2 >= 1 && w2 <= W_)
            v = x[bc * HW_ + (h - 1) * W_ + (w2 - 1)];
        g_xp[e] = v;
    } else {
        int t = e - PAD_ELEMS;
        if (t < KTOT * C_) {
            int oc = t / KTOT, k = t - oc * KTOT;   // k = ci*9 + n
            int ci = k / 9, n = k - ci * 9;
            int R = (ci >> 3) * 72 + n * 8 + (ci & 7);
            g_wt[R * C_ + oc] = w[t];
        }
    }
}

// ============================================================
// K1: f = relu(bn(conv1x1_{64->16}(x)))
// ============================================================
__global__ void k1_conv1(const float* __restrict__ x,
                         const float* __restrict__ w1,
                         const float* __restrict__ g1,
                         const float* __restrict__ b1,
                         const float* __restrict__ m1,
                         const float* __restrict__ v1) {
    __shared__ float ws[C_][HID];
    __shared__ float inv_s[HID], beta_s[HID];
    int tid = threadIdx.x;
    for (int e = tid; e < HID * C_; e += 256) {
        int o = e / C_, c = e % C_;
        ws[c][o] = w1[e];
    }
    if (tid < HID) {
        float inv = g1[tid] * rsqrtf(v1[tid] + 1e-5f);
        inv_s[tid] = inv;
        beta_s[tid] = b1[tid] - m1[tid] * inv;
    }
    __syncthreads();

    int p = blockIdx.x * 256 + tid;
    int b = p >> 14, hw = p & (HW_ - 1);
    const float* xb = x + (size_t)b * C_ * HW_ + hw;

    float acc[HID];
#pragma unroll
    for (int o = 0; o < HID; o++) acc[o] = 0.f;
    for (int c = 0; c < C_; c++) {
        float xv = xb[c * HW_];
#pragma unroll
        for (int o = 0; o < HID; o++) acc[o] += ws[c][o] * xv;
    }
    float* fb = g_f + (size_t)b * HID * HW_ + hw;
#pragma unroll
    for (int o = 0; o < HID; o++)
        fb[o * HW_] = fmaxf(acc[o] * inv_s[o] + beta_s[o], 0.f);
}

// ============================================================
// K2 (tiled): off = relu(bn3(1x1( relu(bn2(3x3(f))) )))
//   block = 16x16 pixel tile, f halo (18x18x16) staged in smem
// ============================================================
__global__ __launch_bounds__(256)
void k2_offsets(const float* __restrict__ wdw,
                const float* __restrict__ g2, const float* __restrict__ b2,
                const float* __restrict__ m2, const float* __restrict__ v2,
                const float* __restrict__ wc2,
                const float* __restrict__ g3, const float* __restrict__ b3,
                const float* __restrict__ m3, const float* __restrict__ v3) {
    __shared__ float fs[HID * 18 * 18];      // [ci][hh][ww] halo tile
    __shared__ float wdw_s[OFC * HID * 9];
    __shared__ float wc2_s[OFC * OFC];
    __shared__ float inv2_s[OFC], beta2_s[OFC], inv3_s[OFC], beta3_s[OFC];
    int tid = threadIdx.x;

    int blk = blockIdx.x;                 // 128 blocks
    int b = blk >> 6, t = blk & 63;
    int h0 = (t >> 3) << 4, w0 = (t & 7) << 4;

    for (int e = tid; e < OFC * HID * 9; e += 256) wdw_s[e] = wdw[e];
    for (int e = tid; e < OFC * OFC; e += 256)     wc2_s[e] = wc2[e];
    if (tid < OFC) {
        float i2 = g2[tid] * rsqrtf(v2[tid] + 1e-5f);
        inv2_s[tid] = i2; beta2_s[tid] = b2[tid] - m2[tid] * i2;
        float i3 = g3[tid] * rsqrtf(v3[tid] + 1e-5f);
        inv3_s[tid] = i3; beta3_s[tid] = b3[tid] - m3[tid] * i3;
    }

    // stage f halo: 16 ci x 18 x 18
    const float* fb = g_f + (size_t)b * HID * HW_;
    for (int e = tid; e < HID * 324; e += 256) {
        int ci = e / 324, r = e - ci * 324;
        int hh = r / 18, ww = r - hh * 18;
        int h = h0 - 1 + hh, w = w0 - 1 + ww;
        float v = 0.f;
        if (h >= 0 && h < H_ && w >= 0 && w < W_)
            v = fb[ci * HW_ + h * W_ + w];
        fs[e] = v;
    }
    __syncthreads();

    int ty2 = tid >> 4, tx2 = tid & 15;     // pixel within tile
    float acc[OFC];
#pragma unroll
    for (int o = 0; o < OFC; o++) acc[o] = 0.f;

    for (int ci = 0; ci < HID; ci++) {
        float fv[9];
        const float* fsc = fs + ci * 324;
#pragma unroll
        for (int dh = 0; dh < 3; dh++)
#pragma unroll
            for (int dw = 0; dw < 3; dw++)
                fv[dh * 3 + dw] = fsc[(ty2 + dh) * 18 + (tx2 + dw)];
        const float* wp = wdw_s + ci * 9;
#pragma unroll
        for (int o = 0; o < OFC; o++) {
            const float* wo = wp + o * (HID * 9);
            float a = acc[o];
#pragma unroll
            for (int k = 0; k < 9; k++) a += wo[k] * fv[k];
            acc[o] = a;
        }
    }
    float tv[OFC];
#pragma unroll
    for (int o = 0; o < OFC; o++)
        tv[o] = fmaxf(acc[o] * inv2_s[o] + beta2_s[o], 0.f);

    int h = h0 + ty2, w = w0 + tx2;
    float* op = g_off + (size_t)b * OFC * HW_ + h * W_ + w;
#pragma unroll
    for (int o2 = 0; o2 < OFC; o2++) {
        float a = 0.f;
#pragma unroll
        for (int o = 0; o < OFC; o++) a += wc2_s[o2 * OFC + o] * tv[o];
        op[o2 * HW_] = fmaxf(a * inv3_s[o2] + beta3_s[o2], 0.f);
    }
}

// ============================================================
// K3: fused bilinear sampler + SGEMM (f32x2) + residual
//   gather: one meta read per (m,n), reused across 8 chunk channels
//   k-order within chunk: j = n*8 + cil   (g_wt pre-permuted to match)
// ============================================================
#define A2N (72*128)
#define K3_SMEM (576*32 + 2*A2N*4)   // 18432 + 73728 = 92160

__global__ __launch_bounds__(256, 2)
void k3_main(const float* __restrict__ x, float* __restrict__ out) {
    extern __shared__ char smem[];
    int4*   idx_s = (int4*)smem;                   // [9][64]
    float4* wgt_s = (float4*)(smem + 9216);        // [9][64]
    float*  a2    = (float*)(smem + 18432);        // [2][72][128]

    int tid = threadIdx.x;
    int blk = blockIdx.x;
    int b = blk >> 8;
    int tile = blk & 255;
    int h0 = (tile >> 4) << 3;
    int w0 = (tile & 15) << 3;

    // ---- bilinear metadata: 64 px x 9 pts ----
    const float* offp = g_off + (size_t)b * OFC * HW_;
    for (int e = tid; e < 64 * NPT; e += 256) {
        int m = e / NPT, n = e - m * NPT;
        int h = h0 + (m >> 3), w = w0 + (m & 7);
        int hw = h * W_ + w;
        float offx = offp[n * HW_ + hw];
        float offy = offp[(NPT + n) * HW_ + hw];
        float px = (float)(h + 1) + (float)(n / 3 - 1) + offx;
        float py = (float)(w + 1) + (float)(n % 3 - 1) + offy;
        float flx = floorf(px), fly = floorf(py);
        float qltx = fminf(fmaxf(flx, 0.f), 129.f);
        float qlty = fminf(fmaxf(fly, 0.f), 129.f);
        float qrbx = fminf(fmaxf(flx + 1.f, 0.f), 129.f);
        float qrby = fminf(fmaxf(fly + 1.f, 0.f), 129.f);
        px = fminf(fmaxf(px, 0.f), 129.f);
        py = fminf(fmaxf(py, 0.f), 129.f);
        float gxl = 1.f + qltx - px, gxr = 1.f - qrbx + px;
        float gyl = 1.f + qlty - py, gyr = 1.f - qrby + py;
        float4 g;
        g.x = gxl * gyl; g.y = gxr * gyr; g.z = gxl * gyr; g.w = gxr * gyl;
        int ltx = (int)qltx, lty = (int)qlty, rbx = (int)qrbx, rby = (int)qrby;
        int4 id;
        id.x = ltx * WP_ + lty;
        id.y = rbx * WP_ + rby;
        id.z = ltx * WP_ + rby;
        id.w = rbx * WP_ + lty;
        idx_s[n * 64 + m] = id;     // [n][m] layout
        wgt_s[n * 64 + m] = g;
    }
    __syncthreads();

    const float* xpb = g_xp + (size_t)b * C_ * HWP_;

    // ---- gather chunk 0 into buffer 0 ----
    {
        float* ab = a2;
        const float* xc0 = xpb;
        for (int e = tid; e < 576; e += 256) {
            int n = e >> 6, m = e & 63;
            int4 id = idx_s[e];
            float4 g = wgt_s[e];
            float* dst = ab + ((n << 3) << 7) + (m << 1);
#pragma unroll
            for (int cil = 0; cil < 8; cil++) {
                const float* xc = xc0 + cil * HWP_;
                float v = g.x * xc[id.x] + g.y * xc[id.y]
                        + g.z * xc[id.z] + g.w * xc[id.w];
                *reinterpret_cast<float2*>(dst + (cil << 7)) = make_float2(v, v);
            }
        }
    }

    int tx = tid & 15, ty = tid >> 4;
    unsigned long long acc[4][2];
#pragma unroll
    for (int i = 0; i < 4; i++) { acc[i][0] = 0ull; acc[i][1] = 0ull; }

    const int tyo = ty << 3;
    const int txo = tx << 2;

    // ---- pipelined chunk loop: gather(c+1) overlaps GEMM(c) ----
    for (int c = 0; c < 8; c++) {
        __syncthreads();

        if (c < 7) {
            float* ab = a2 + ((c + 1) & 1) * A2N;
            const float* xc0 = xpb + (c + 1) * 8 * HWP_;
            for (int e = tid; e < 576; e += 256) {
                int n = e >> 6, m = e & 63;
                int4 id = idx_s[e];
                float4 g = wgt_s[e];
                float* dst = ab + ((n << 3) << 7) + (m << 1);
#pragma unroll
                for (int cil = 0; cil < 8; cil++) {
                    const float* xc = xc0 + cil * HWP_;
                    float v = g.x * xc[id.x] + g.y * xc[id.y]
                            + g.z * xc[id.z] + g.w * xc[id.w];
                    *reinterpret_cast<float2*>(dst + (cil << 7)) = make_float2(v, v);
                }
            }
        }

        const float* ab = a2 + (c & 1) * A2N;
        const float* wp = g_wt + c * 72 * C_ + txo;   // permuted B rows (L2-hot)
#pragma unroll 8
        for (int k = 0; k < 72; k++) {
            ulonglong2 bb = *reinterpret_cast<const ulonglong2*>(wp + (k << 6));
            ulonglong2 aA = *reinterpret_cast<const ulonglong2*>(ab + (k << 7) + tyo);
            ulonglong2 aB = *reinterpret_cast<const ulonglong2*>(ab + (k << 7) + tyo + 4);
            FMA2(acc[0][0], aA.x, bb.x); FMA2(acc[0][1], aA.x, bb.y);
            FMA2(acc[1][0], aA.y, bb.x); FMA2(acc[1][1], aA.y, bb.y);
            FMA2(acc[2][0], aB.x, bb.x); FMA2(acc[2][1], aB.x, bb.y);
            FMA2(acc[3][0], aB.y, bb.x); FMA2(acc[3][1], aB.y, bb.y);
        }
    }

    // ---- epilogue: stage through smem (buf0 is dead) for coalesced stores ----
    float* sa = a2;  // [oc][m]
#pragma unroll
    for (int pi = 0; pi < 4; pi++) {
        int m = (ty << 2) + pi;
#pragma unroll
        for (int j = 0; j < 2; j++) {
            unsigned long long v = acc[pi][j];
            float lo = __uint_as_float((unsigned)(v & 0xffffffffull));
            float hi = __uint_as_float((unsigned)(v >> 32));
            sa[(txo + 2 * j) * 64 + m]     = lo;
            sa[(txo + 2 * j + 1) * 64 + m] = hi;
        }
    }
    __syncthreads();

    for (int e = tid; e < 64 * 64; e += 256) {
        int oc = e >> 6, m = e & 63;
        int h = h0 + (m >> 3), w = w0 + (m & 7);
        int gi = ((b * C_ + oc) * H_ + h) * W_ + w;
        out[gi] = x[gi] + sa[e];
    }
}

// ============================================================
extern "C" void kernel_launch(void* const* d_in, const int* in_sizes, int n_in,
                              void* d_out, int out_size) {
    const float* x       = (const float*)d_in[0];
    const float* w_conv1 = (const float*)d_in[1];
    const float* g1 = (const float*)d_in[2];
    const float* b1 = (const float*)d_in[3];
    const float* m1 = (const float*)d_in[4];
    const float* v1 = (const float*)d_in[5];
    const float* w_dw = (const float*)d_in[6];
    const float* g2 = (const float*)d_in[7];
    const float* b2 = (const float*)d_in[8];
    const float* m2 = (const float*)d_in[9];
    const float* v2 = (const float*)d_in[10];
    const float* w_conv2 = (const float*)d_in[11];
    const float* g3 = (const float*)d_in[12];
    const float* b3 = (const float*)d_in[13];
    const float* m3 = (const float*)d_in[14];
    const float* v3 = (const float*)d_in[15];
    const float* w_out = (const float*)d_in[16];
    float* out = (float*)d_out;

    cudaFuncSetAttribute(k3_main, cudaFuncAttributeMaxDynamicSharedMemorySize, K3_SMEM);

    k_pad0<<<(PAD_ELEMS + KTOT*C_ + 255) / 256, 256>>>(x, w_out);
    k1_conv1<<<PIXT / 256, 256>>>(x, w_conv1, g1, b1, m1, v1);
    k2_offsets<<<128, 256>>>(w_dw, g2, b2, m2, v2, w_conv2, g3, b3, m3, v3);
    k3_main<<<B_ * (H_ / 8) * (W_ / 8), 256, K3_SMEM>>>(x, out);
}